// round 1
// baseline (speedup 1.0000x reference)
#include <cuda_runtime.h>

#define B_   4
#define S_   2048
#define H_   16
#define HID_ 2048
#define DK_  128
#define DV_  128
#define P_   (B_*S_)   // 8192 positions

// scratch (allowed: __device__ globals)
__device__ float g_decay[P_*H_];
__device__ float g_beta [P_*H_];

// ============================================================
// Kernel 1: gating GEMM  raw = x @ [Wa;Wb]^T  + epilogue
// tile: 64 positions x 32 outputs, K-chunk 32, 256 threads
// ============================================================
#define GT_POS 64
#define GT_K   32

__global__ __launch_bounds__(256) void gate_kernel(
    const float* __restrict__ x,
    const float* __restrict__ Wa, const float* __restrict__ Wb,
    const float* __restrict__ dt_bias, const float* __restrict__ A_log)
{
    __shared__ float xs[GT_POS][GT_K+1];
    __shared__ float ws[32][GT_K+1];
    int t  = threadIdx.x;
    int p0 = blockIdx.x * GT_POS;
    int tx = t & 7;   // output group: f = 4*tx + j
    int ty = t >> 3;  // position group: p = p0 + 2*ty + i
    float acc[2][4] = {};

    for (int kc = 0; kc < HID_; kc += GT_K) {
        #pragma unroll
        for (int i = 0; i < (GT_POS*GT_K)/256; ++i) {   // 8
            int e = i*256 + t; int r = e >> 5, c = e & 31;
            xs[r][c] = x[(size_t)(p0 + r)*HID_ + kc + c];
        }
        #pragma unroll
        for (int i = 0; i < (32*GT_K)/256; ++i) {       // 4
            int e = i*256 + t; int f = e >> 5, c = e & 31;
            const float* wrow = (f < 16) ? (Wa + f*HID_) : (Wb + (f-16)*HID_);
            ws[f][c] = wrow[kc + c];
        }
        __syncthreads();
        #pragma unroll
        for (int k = 0; k < GT_K; ++k) {
            float xv0 = xs[2*ty  ][k];
            float xv1 = xs[2*ty+1][k];
            #pragma unroll
            for (int j = 0; j < 4; ++j) {
                float wv = ws[4*tx+j][k];
                acc[0][j] = fmaf(xv0, wv, acc[0][j]);
                acc[1][j] = fmaf(xv1, wv, acc[1][j]);
            }
        }
        __syncthreads();
    }

    #pragma unroll
    for (int i = 0; i < 2; ++i) {
        int p = p0 + 2*ty + i;
        #pragma unroll
        for (int j = 0; j < 4; ++j) {
            int f = 4*tx + j;
            float r = acc[i][j];
            if (f < 16) {
                // alpha = -exp(A_log)*softplus(r + dt_bias); decay = exp(alpha)
                float z  = r + __ldg(dt_bias + f);
                float sp = fmaxf(z, 0.0f) + log1pf(expf(-fabsf(z)));
                g_decay[p*H_ + f] = expf(-expf(__ldg(A_log + f)) * sp);
            } else {
                g_beta[p*H_ + (f-16)] = r;
            }
        }
    }
}

// ============================================================
// Kernel 2: delta-rule scan.
// One warp per (b, h, 8-column slice of DV): 1024 blocks x 32 thr.
// Lane layout: lk = lane&7 owns 16 contiguous DK rows (as 8 f32x2
// row-pairs); lv = lane>>3 owns 2 DV columns. State in registers.
// Math per step (per (b,h)):
//   p = k.S_old, o = q.S_old, qk = q.k        (one pass)
//   d[c] = (v[c] - g*p[c]) * beta
//   S_new = g*S_old + k (x) d                 (one pass, f32x2)
//   out[c] = g*o[c] + qk*d[c]
// ============================================================
typedef unsigned long long u64;

__device__ __forceinline__ u64 fma2(u64 a, u64 b, u64 c) {
    u64 d; asm("fma.rn.f32x2 %0, %1, %2, %3;" : "=l"(d) : "l"(a), "l"(b), "l"(c));
    return d;
}
__device__ __forceinline__ u64 mul2(u64 a, u64 b) {
    u64 d; asm("mul.rn.f32x2 %0, %1, %2;" : "=l"(d) : "l"(a), "l"(b));
    return d;
}
__device__ __forceinline__ u64 pack2(float x, float y) {
    u64 d; asm("mov.b64 %0, {%1, %2};" : "=l"(d)
               : "r"(__float_as_uint(x)), "r"(__float_as_uint(y)));
    return d;
}
__device__ __forceinline__ float hadd2(u64 a) {
    unsigned lo, hi;
    asm("mov.b64 {%0, %1}, %2;" : "=r"(lo), "=r"(hi) : "l"(a));
    return __uint_as_float(lo) + __uint_as_float(hi);
}

struct Step {
    u64 k2[8], q2[8];
    float v0, v1, g, b;
};

__device__ __forceinline__ void load_step(Step& d,
    const float* kb, const float* qb, const float* vb,
    const float* gb, const float* bb, int s, int lk, int vhalf)
{
    size_t off = (size_t)s * (H_*DK_);
    const ulonglong2* kp = (const ulonglong2*)(kb + off + lk*16);
    const ulonglong2* qp = (const ulonglong2*)(qb + off + lk*16);
    #pragma unroll
    for (int i = 0; i < 4; ++i) {
        ulonglong2 kk = __ldg(kp + i);
        d.k2[2*i] = kk.x; d.k2[2*i+1] = kk.y;
        ulonglong2 qq = __ldg(qp + i);
        d.q2[2*i] = qq.x; d.q2[2*i+1] = qq.y;
    }
    float2 vv = __ldg((const float2*)(vb + off) + vhalf);
    d.v0 = vv.x; d.v1 = vv.y;
    d.g = __ldg(gb + (size_t)s*H_);
    d.b = __ldg(bb + (size_t)s*H_);
}

__device__ __forceinline__ void do_step(const Step& c, u64 st[8][2],
                                        float* outp, int lk, int vhalf)
{
    u64 p2a = 0, p2b = 0, o2a = 0, o2b = 0, qk2 = 0;
    #pragma unroll
    for (int j = 0; j < 8; ++j) {
        p2a = fma2(c.k2[j], st[j][0], p2a);
        p2b = fma2(c.k2[j], st[j][1], p2b);
        o2a = fma2(c.q2[j], st[j][0], o2a);
        o2b = fma2(c.q2[j], st[j][1], o2b);
        qk2 = fma2(c.q2[j], c.k2[j], qk2);
    }
    float p0 = hadd2(p2a), p1 = hadd2(p2b);
    float o0 = hadd2(o2a), o1 = hadd2(o2b);
    float qk = hadd2(qk2);
    #pragma unroll
    for (int m = 1; m < 8; m <<= 1) {
        p0 += __shfl_xor_sync(0xffffffffu, p0, m);
        p1 += __shfl_xor_sync(0xffffffffu, p1, m);
        o0 += __shfl_xor_sync(0xffffffffu, o0, m);
        o1 += __shfl_xor_sync(0xffffffffu, o1, m);
        qk += __shfl_xor_sync(0xffffffffu, qk, m);
    }
    float g = c.g, bb = c.b;
    float d0 = (c.v0 - g*p0) * bb;
    float d1 = (c.v1 - g*p1) * bb;
    u64 g2 = pack2(g, g), d0_2 = pack2(d0, d0), d1_2 = pack2(d1, d1);
    #pragma unroll
    for (int j = 0; j < 8; ++j) {
        st[j][0] = fma2(c.k2[j], d0_2, mul2(g2, st[j][0]));
        st[j][1] = fma2(c.k2[j], d1_2, mul2(g2, st[j][1]));
    }
    if (lk == 0) {
        float2 o;
        o.x = fmaf(g, o0, qk*d0);
        o.y = fmaf(g, o1, qk*d1);
        ((float2*)outp)[vhalf] = o;
    }
}

__global__ void __launch_bounds__(32) scan_kernel(
    const float* __restrict__ q, const float* __restrict__ k,
    const float* __restrict__ v, float* __restrict__ out)
{
    int bid  = blockIdx.x;
    int colg = bid & 15;         // 16 column groups of 8
    int bh   = bid >> 4;
    int b    = bh >> 4, h = bh & 15;
    int l    = threadIdx.x;
    int lk   = l & 7, lv = l >> 3;
    int col_base = colg * 8;
    int vhalf = (col_base >> 1) + lv;

    size_t base = ((size_t)b * S_ * H_ + h) * DK_;
    const float* kb = k + base;
    const float* qb = q + base;
    const float* vb = v + base;
    float*       ob = out + base;
    const float* gb = g_decay + (size_t)b * S_ * H_ + h;
    const float* bb = g_beta  + (size_t)b * S_ * H_ + h;

    u64 st[8][2];
    #pragma unroll
    for (int j = 0; j < 8; ++j) { st[j][0] = 0ull; st[j][1] = 0ull; }

    Step A, Bs;
    load_step(A, kb, qb, vb, gb, bb, 0, lk, vhalf);

    for (int s = 0; s < S_; s += 2) {
        load_step(Bs, kb, qb, vb, gb, bb, s+1, lk, vhalf);
        do_step(A, st, ob + (size_t)s*(H_*DV_), lk, vhalf);
        if (s + 2 < S_)
            load_step(A, kb, qb, vb, gb, bb, s+2, lk, vhalf);
        do_step(Bs, st, ob + (size_t)(s+1)*(H_*DV_), lk, vhalf);
    }
}

// ============================================================
extern "C" void kernel_launch(void* const* d_in, const int* in_sizes, int n_in,
                              void* d_out, int out_size)
{
    (void)in_sizes; (void)n_in; (void)out_size;
    const float* x   = (const float*)d_in[0];
    const float* q   = (const float*)d_in[1];
    const float* k   = (const float*)d_in[2];
    const float* v   = (const float*)d_in[3];
    const float* Wa  = (const float*)d_in[4];
    const float* Wb  = (const float*)d_in[5];
    const float* dtb = (const float*)d_in[6];
    const float* Al  = (const float*)d_in[7];
    float* out = (float*)d_out;

    gate_kernel<<<P_/GT_POS, 256>>>(x, Wa, Wb, dtb, Al);
    scan_kernel<<<B_*H_*(DV_/8), 32>>>(q, k, v, out);
}

// round 2
// speedup vs baseline: 1.4457x; 1.4457x over previous
#include <cuda_runtime.h>

#define B_   4
#define S_   2048
#define H_   16
#define HID_ 2048
#define DK_  128
#define DV_  128
#define P_   (B_*S_)   // 8192 positions

// scratch (allowed: __device__ globals)
__device__ float g_decay[P_*H_];
__device__ float g_beta [P_*H_];

// ============================================================
// Kernel 1: gating GEMM  raw = x @ [Wa;Wb]^T  + epilogue
// ============================================================
#define GT_POS 64
#define GT_K   32

__global__ __launch_bounds__(256) void gate_kernel(
    const float* __restrict__ x,
    const float* __restrict__ Wa, const float* __restrict__ Wb,
    const float* __restrict__ dt_bias, const float* __restrict__ A_log)
{
    __shared__ float xs[GT_POS][GT_K+1];
    __shared__ float ws[32][GT_K+1];
    int t  = threadIdx.x;
    int p0 = blockIdx.x * GT_POS;
    int tx = t & 7;   // output group: f = 4*tx + j
    int ty = t >> 3;  // position group: p = p0 + 2*ty + i
    float acc[2][4] = {};

    for (int kc = 0; kc < HID_; kc += GT_K) {
        #pragma unroll
        for (int i = 0; i < (GT_POS*GT_K)/256; ++i) {
            int e = i*256 + t; int r = e >> 5, c = e & 31;
            xs[r][c] = x[(size_t)(p0 + r)*HID_ + kc + c];
        }
        #pragma unroll
        for (int i = 0; i < (32*GT_K)/256; ++i) {
            int e = i*256 + t; int f = e >> 5, c = e & 31;
            const float* wrow = (f < 16) ? (Wa + f*HID_) : (Wb + (f-16)*HID_);
            ws[f][c] = wrow[kc + c];
        }
        __syncthreads();
        #pragma unroll
        for (int k = 0; k < GT_K; ++k) {
            float xv0 = xs[2*ty  ][k];
            float xv1 = xs[2*ty+1][k];
            #pragma unroll
            for (int j = 0; j < 4; ++j) {
                float wv = ws[4*tx+j][k];
                acc[0][j] = fmaf(xv0, wv, acc[0][j]);
                acc[1][j] = fmaf(xv1, wv, acc[1][j]);
            }
        }
        __syncthreads();
    }

    #pragma unroll
    for (int i = 0; i < 2; ++i) {
        int p = p0 + 2*ty + i;
        #pragma unroll
        for (int j = 0; j < 4; ++j) {
            int f = 4*tx + j;
            float r = acc[i][j];
            if (f < 16) {
                float z  = r + __ldg(dt_bias + f);
                float sp = fmaxf(z, 0.0f) + log1pf(expf(-fabsf(z)));
                g_decay[p*H_ + f] = expf(-expf(__ldg(A_log + f)) * sp);
            } else {
                g_beta[p*H_ + (f-16)] = r;
            }
        }
    }
}

// ============================================================
// Kernel 2: delta-rule scan.
// Warp per (b,h, 8 DV cols). lane=(lk:0..7, lv:0..3).
// Each lane loads a DISTINCT coalesced 16B of k and q
// (slot = lk*4+lv), then a 2-stage xor butterfly all-gathers the
// 8 row-pairs of group lk. The per-lane ordering permutation is
// static & identical for k/q, and all consumers are sums over j,
// so no reordering is needed.
// ============================================================
typedef unsigned long long u64;

__device__ __forceinline__ u64 fma2(u64 a, u64 b, u64 c) {
    u64 d; asm("fma.rn.f32x2 %0, %1, %2, %3;" : "=l"(d) : "l"(a), "l"(b), "l"(c));
    return d;
}
__device__ __forceinline__ u64 mul2(u64 a, u64 b) {
    u64 d; asm("mul.rn.f32x2 %0, %1, %2;" : "=l"(d) : "l"(a), "l"(b));
    return d;
}
__device__ __forceinline__ u64 pack2(float x, float y) {
    u64 d; asm("mov.b64 %0, {%1, %2};" : "=l"(d)
               : "r"(__float_as_uint(x)), "r"(__float_as_uint(y)));
    return d;
}
__device__ __forceinline__ float hadd2(u64 a) {
    unsigned lo, hi;
    asm("mov.b64 {%0, %1}, %2;" : "=r"(lo), "=r"(hi) : "l"(a));
    return __uint_as_float(lo) + __uint_as_float(hi);
}

struct Raw  { u64 kx, ky, qx, qy; float2 v; float g, b; };
struct Gath { u64 k2[8], q2[8]; float v0, v1, g, b; };

__device__ __forceinline__ void load_raw(Raw& r,
    const float* kb, const float* qb, const float* vb,
    const float* gb, const float* bb, int s, int slot, int vhalf)
{
    size_t off = (size_t)s * (H_*DK_);
    ulonglong2 kk = __ldg((const ulonglong2*)(kb + off) + slot);
    r.kx = kk.x; r.ky = kk.y;
    ulonglong2 qq = __ldg((const ulonglong2*)(qb + off) + slot);
    r.qx = qq.x; r.qy = qq.y;
    r.v = __ldg((const float2*)(vb + off) + vhalf);
    r.g = __ldg(gb + (size_t)s*H_);
    r.b = __ldg(bb + (size_t)s*H_);
}

__device__ __forceinline__ void gather(Gath& g, const Raw& r)
{
    const unsigned m = 0xffffffffu;
    g.k2[0] = r.kx;
    g.k2[1] = r.ky;
    g.k2[2] = __shfl_xor_sync(m, r.kx, 8);
    g.k2[3] = __shfl_xor_sync(m, r.ky, 8);
    g.k2[4] = __shfl_xor_sync(m, g.k2[0], 16);
    g.k2[5] = __shfl_xor_sync(m, g.k2[1], 16);
    g.k2[6] = __shfl_xor_sync(m, g.k2[2], 16);
    g.k2[7] = __shfl_xor_sync(m, g.k2[3], 16);
    g.q2[0] = r.qx;
    g.q2[1] = r.qy;
    g.q2[2] = __shfl_xor_sync(m, r.qx, 8);
    g.q2[3] = __shfl_xor_sync(m, r.qy, 8);
    g.q2[4] = __shfl_xor_sync(m, g.q2[0], 16);
    g.q2[5] = __shfl_xor_sync(m, g.q2[1], 16);
    g.q2[6] = __shfl_xor_sync(m, g.q2[2], 16);
    g.q2[7] = __shfl_xor_sync(m, g.q2[3], 16);
    g.v0 = r.v.x; g.v1 = r.v.y; g.g = r.g; g.b = r.b;
}

__device__ __forceinline__ void do_step(const Gath& c, u64 st[8][2],
                                        float* outp, int lk, int vhalf)
{
    u64 p2a = 0, p2b = 0, o2a = 0, o2b = 0, qk2 = 0;
    #pragma unroll
    for (int j = 0; j < 8; ++j) {
        p2a = fma2(c.k2[j], st[j][0], p2a);
        p2b = fma2(c.k2[j], st[j][1], p2b);
        o2a = fma2(c.q2[j], st[j][0], o2a);
        o2b = fma2(c.q2[j], st[j][1], o2b);
        qk2 = fma2(c.q2[j], c.k2[j], qk2);
    }
    float p0 = hadd2(p2a), p1 = hadd2(p2b);
    float o0 = hadd2(o2a), o1 = hadd2(o2b);
    float qk = hadd2(qk2);
    // reduce over lk (lanes with same lv): xor 1,2,4
    #pragma unroll
    for (int m = 1; m < 8; m <<= 1) {
        p0 += __shfl_xor_sync(0xffffffffu, p0, m);
        p1 += __shfl_xor_sync(0xffffffffu, p1, m);
        o0 += __shfl_xor_sync(0xffffffffu, o0, m);
        o1 += __shfl_xor_sync(0xffffffffu, o1, m);
        qk += __shfl_xor_sync(0xffffffffu, qk, m);
    }
    float g = c.g, bb = c.b;
    float d0 = (c.v0 - g*p0) * bb;
    float d1 = (c.v1 - g*p1) * bb;
    u64 g2 = pack2(g, g), d0_2 = pack2(d0, d0), d1_2 = pack2(d1, d1);
    #pragma unroll
    for (int j = 0; j < 8; ++j) {
        st[j][0] = fma2(c.k2[j], d0_2, mul2(g2, st[j][0]));
        st[j][1] = fma2(c.k2[j], d1_2, mul2(g2, st[j][1]));
    }
    if (lk == 0) {
        float2 o;
        o.x = fmaf(g, o0, qk*d0);
        o.y = fmaf(g, o1, qk*d1);
        ((float2*)outp)[vhalf] = o;
    }
}

__global__ void __launch_bounds__(32) scan_kernel(
    const float* __restrict__ q, const float* __restrict__ k,
    const float* __restrict__ v, float* __restrict__ out)
{
    int bid  = blockIdx.x;
    int colg = bid & 15;         // 16 column groups of 8
    int bh   = bid >> 4;
    int b    = bh >> 4, h = bh & 15;
    int l    = threadIdx.x;
    int lk   = l & 7, lv = l >> 3;
    int slot = lk*4 + lv;        // distinct 16B per lane, coalesced
    int vhalf = colg*4 + lv;     // float2 index into the 128-col v/out row

    size_t base = ((size_t)b * S_ * H_ + h) * DK_;
    const float* kb = k + base;
    const float* qb = q + base;
    const float* vb = v + base;
    float*       ob = out + base;
    const float* gb = g_decay + (size_t)b * S_ * H_ + h;
    const float* bb = g_beta  + (size_t)b * S_ * H_ + h;

    u64 st[8][2];
    #pragma unroll
    for (int j = 0; j < 8; ++j) { st[j][0] = 0ull; st[j][1] = 0ull; }

    // pipeline: ldg(s+2) -> gather(s+1) -> compute(s)
    Raw r0, r1, rt;
    Gath gA, gB;
    load_raw(r0, kb, qb, vb, gb, bb, 0, slot, vhalf);
    load_raw(r1, kb, qb, vb, gb, bb, 1, slot, vhalf);
    gather(gA, r0);

    for (int s = 0; s < S_; s += 2) {
        int i2 = (s+2 < S_) ? s+2 : S_-1;
        int i3 = (s+3 < S_) ? s+3 : S_-1;
        load_raw(rt, kb, qb, vb, gb, bb, i2, slot, vhalf);
        gather(gB, r1);                               // r1 loaded one iter ago
        do_step(gA, st, ob + (size_t)s*(H_*DV_), lk, vhalf);
        load_raw(r1, kb, qb, vb, gb, bb, i3, slot, vhalf);
        gather(gA, rt);                               // rt loaded ~1 step ago
        do_step(gB, st, ob + (size_t)(s+1)*(H_*DV_), lk, vhalf);
        r0 = rt;
    }
}

// ============================================================
extern "C" void kernel_launch(void* const* d_in, const int* in_sizes, int n_in,
                              void* d_out, int out_size)
{
    (void)in_sizes; (void)n_in; (void)out_size;
    const float* x   = (const float*)d_in[0];
    const float* q   = (const float*)d_in[1];
    const float* k   = (const float*)d_in[2];
    const float* v   = (const float*)d_in[3];
    const float* Wa  = (const float*)d_in[4];
    const float* Wb  = (const float*)d_in[5];
    const float* dtb = (const float*)d_in[6];
    const float* Al  = (const float*)d_in[7];
    float* out = (float*)d_out;

    gate_kernel<<<P_/GT_POS, 256>>>(x, Wa, Wb, dtb, Al);
    scan_kernel<<<B_*H_*(DV_/8), 32>>>(q, k, v, out);
}